// round 7
// baseline (speedup 1.0000x reference)
#include <cuda_runtime.h>
#include <math.h>

#define HALF_DT 0.005f
#define BATCH   32
#define DM      2048
#define DV      2047
#define DL      512
#define KH      256     // K-half per CTA (split-K by 2)
#define DPC     32      // d-rows per CTA
#define ZSTR    260     // 256 + 4 pad: conflict-free LDS.128 (4*lane mod 32 pattern)
#define NT      256
#define GRID    128

// split-K partial pre-activations: g_pre[khalf][b][d]
__device__ float g_pre[2][BATCH][DM];
// replay-safe grid barrier state (monotonic across graph replays)
__device__ unsigned long long g_cnt = 0ULL;
__device__ unsigned long long g_rel = 0ULL;

extern __shared__ float smem[];

__global__ void __launch_bounds__(NT, 1)
fused_kernel(const float* __restrict__ z0,
             const float* __restrict__ h,
             const float* __restrict__ W,
             const float* __restrict__ bias,
             float* __restrict__ out) {
    const int tid   = threadIdx.x;
    const int cid   = blockIdx.x;
    const int lane  = tid & 31;
    const int w     = tid >> 5;           // 0..7
    const int khalf = cid >> 6;           // 0,1
    const int dbase = (cid & 63) * DPC;   // 0..2016
    const int kbase = khalf * KH;

    // ---------------- phase 1: GEMM partial (all 128 CTAs) ----------------
    float* zs = smem;                 // [32][ZSTR]
    float* ws = smem + BATCH * ZSTR;  // [32][ZSTR]

    // stage z0 chunk [32 x 256] (coalesced within rows)
    for (int idx = tid; idx < BATCH * KH; idx += NT) {
        int b  = idx >> 8;
        int kk = idx & 255;
        zs[b * ZSTR + kk] = z0[b * DL + kbase + kk];
    }
    // stage W tile [32 x 256] via coalesced float4 (high MLP)
    for (int idx = tid; idx < DPC * (KH / 4); idx += NT) {   // 2048 vec4s, 8/thread
        int r  = idx >> 6;          // d-row 0..31
        int c4 = idx & 63;
        int d  = dbase + r; if (d > DV - 1) d = DV - 1;      // clamp d=2047 (unused)
        float4 v = __ldg((const float4*)(W + (size_t)d * DL + kbase) + c4);
        *((float4*)(ws + r * ZSTR) + c4) = v;
    }
    __syncthreads();

    {
        const float4* zrow = (const float4*)(zs + lane * ZSTR);
        const float4* w0 = (const float4*)(ws + (w     ) * ZSTR);
        const float4* w1 = (const float4*)(ws + (w +  8) * ZSTR);
        const float4* w2 = (const float4*)(ws + (w + 16) * ZSTR);
        const float4* w3 = (const float4*)(ws + (w + 24) * ZSTR);
        float a0 = 0.f, a1 = 0.f, a2 = 0.f, a3 = 0.f;
#pragma unroll 8
        for (int k = 0; k < KH / 4; k++) {
            float4 z = zrow[k];
            float4 p = w0[k];   // uniform LDS -> broadcast, 1 crossbar cyc
            a0 += z.x * p.x + z.y * p.y + z.z * p.z + z.w * p.w;
            float4 q = w1[k];
            a1 += z.x * q.x + z.y * q.y + z.z * q.z + z.w * q.w;
            float4 r = w2[k];
            a2 += z.x * r.x + z.y * r.y + z.z * r.z + z.w * r.w;
            float4 s = w3[k];
            a3 += z.x * s.x + z.y * s.y + z.z * s.z + z.w * s.w;
        }
        g_pre[khalf][lane][dbase + w     ] = a0;
        g_pre[khalf][lane][dbase + w +  8] = a1;
        g_pre[khalf][lane][dbase + w + 16] = a2;
        g_pre[khalf][lane][dbase + w + 24] = a3;
    }

    // ---------------- grid barrier (replay-safe) ----------------
    __threadfence();          // each thread publishes its g_pre stores
    __syncthreads();          // all fences done before the CTA arrives
    unsigned long long gen = 0ULL;
    if (tid == 0) {
        unsigned long long a = atomicAdd(&g_cnt, 1ULL);
        gen = a >> 7;                                   // same for all 128 arrivals of a launch
        if ((a & 127ULL) == 127ULL)
            atomicExch(&g_rel, gen + 1ULL);             // last arriver releases
    }
    if (cid >= BATCH) return;                           // 96 CTAs done

    if (tid == 0)
        while (atomicAdd(&g_rel, 0ULL) <= gen) __nanosleep(64);
    __syncthreads();
    __threadfence();                                    // acquire

    // ---------------- phase 2: Neumann Cayley solve (CTAs 0..31) ----------------
    // x = (I-N)^{-1}(I+N)h = h + 2Nh + 2N^2h + 2N^3h + O(1e-8),  ||N||<=0.01
    // (N x)[i] = sv[i]*x[i+1] - sv[i-1]*x[i-1],  sv = HALF_DT*tanh(pre+bias)
    const int b = cid;
    float* hp  = smem + 1;              // [-1..2048]
    float* svp = smem + 2056 + 1;
    float* y1  = smem + 4112 + 1;
    float* y2  = smem + 6168 + 1;

    if (tid == 0) {
        hp[-1] = 0.f;  hp[DM] = 0.f;
        svp[-1] = 0.f; svp[DV] = 0.f;
        y1[-1] = 0.f;  y1[DM] = 0.f;
        y2[-1] = 0.f;  y2[DM] = 0.f;
    }
    const float* p0   = g_pre[0][b];
    const float* p1   = g_pre[1][b];
    const float* hrow = h + (size_t)b * DM;
#pragma unroll
    for (int j = 0; j < DM / NT; j++) {       // 8
        int i = tid + j * NT;
        hp[i] = hrow[i];
        if (i < DV)
            svp[i] = HALF_DT * tanhf(p0[i] + p1[i] + __ldg(&bias[i]));
    }
    __syncthreads();

    float acc[DM / NT];
#pragma unroll
    for (int j = 0; j < DM / NT; j++) {       // pass 1: y1 = N h
        int i = tid + j * NT;
        float t = svp[i] * hp[i + 1] - svp[i - 1] * hp[i - 1];
        y1[i] = t;
        acc[j] = hp[i] + 2.f * t;
    }
    __syncthreads();
#pragma unroll
    for (int j = 0; j < DM / NT; j++) {       // pass 2: y2 = N y1
        int i = tid + j * NT;
        float t = svp[i] * y1[i + 1] - svp[i - 1] * y1[i - 1];
        y2[i] = t;
        acc[j] += 2.f * t;
    }
    __syncthreads();
    float* orow = out + (size_t)b * DM;
#pragma unroll
    for (int j = 0; j < DM / NT; j++) {       // pass 3 + store
        int i = tid + j * NT;
        float t = svp[i] * y2[i + 1] - svp[i - 1] * y2[i - 1];
        orow[i] = acc[j] + 2.f * t;
    }
}

// ---------------------------------------------------------------------------
extern "C" void kernel_launch(void* const* d_in, const int* in_sizes, int n_in,
                              void* d_out, int out_size) {
    const float* z0   = (const float*)d_in[0];   // (32, 512)
    const float* h    = (const float*)d_in[1];   // (32, 2048)
    const float* W    = (const float*)d_in[2];   // (2047, 512)
    const float* bias = (const float*)d_in[3];   // (2047,)
    float* out = (float*)d_out;                  // (32, 2048)

    const int smemB = 2 * BATCH * ZSTR * (int)sizeof(float);   // 66560 B
    static bool attr_done = false;
    if (!attr_done) {
        cudaFuncSetAttribute(fused_kernel,
                             cudaFuncAttributeMaxDynamicSharedMemorySize, smemB);
        attr_done = true;
    }
    fused_kernel<<<GRID, NT, smemB>>>(z0, h, W, bias, out);
}

// round 8
// speedup vs baseline: 1.5754x; 1.5754x over previous
#include <cuda_runtime.h>
#include <math.h>

#define HALF_DT 0.005f
#define BATCH   32
#define DM      2048
#define DV      2047
#define DL      512
#define KS      4            // split-K factor
#define KH      (DL / KS)    // 128 k per CTA
#define DPC     64           // d-rows per CTA
#define NGR     (DM / DPC)   // 32 d-groups
#define GRID    (KS * NGR)   // 128 CTAs
#define NT      512
#define ZSTR    (KH + 4)     // 132: conflict-free LDS.128 (4*lane mod 32 covers all banks)
#define TSTR    33           // transpose buffer stride (odd -> conflict-free)

// split-K partial pre-activations: g_pre[kq][b][d]  (coalesced writes & reads)
__device__ float g_pre[KS][BATCH][DM];

extern __shared__ float smem[];

// ---------------------------------------------------------------------------
// GEMM partials: 128 CTAs x 512 threads. CTA = (kq, d-group of 64 rows).
// Stage z chunk [32 x 128] + W tile [64 x 128] in smem (coalesced float4),
// mainloop: warp w -> rows w+{0,16,32,48}, lane = batch. Crossbar/FFMA balanced.
// ---------------------------------------------------------------------------
__global__ void __launch_bounds__(NT, 1)
gemm_kernel(const float* __restrict__ z0,
            const float* __restrict__ W) {
    const int tid  = threadIdx.x;
    const int lane = tid & 31;
    const int w    = tid >> 5;            // 0..15
    const int kq    = blockIdx.x >> 5;    // 0..3
    const int grp   = blockIdx.x & 31;
    const int dbase = grp * DPC;
    const int kbase = kq * KH;

    float* zs = smem;                     // [32][ZSTR]
    float* ws = smem + BATCH * ZSTR;      // [64][ZSTR]

    // stage z chunk (4096 floats)
    for (int idx = tid; idx < BATCH * KH; idx += NT) {
        int b  = idx >> 7;
        int kk = idx & (KH - 1);
        zs[b * ZSTR + kk] = z0[b * DL + kbase + kk];
    }
    // stage W tile (2048 float4, coalesced, 4 per thread)
#pragma unroll
    for (int idx = tid; idx < DPC * (KH / 4); idx += NT) {
        int r  = idx >> 5;                // 0..63
        int c4 = idx & 31;
        int d  = dbase + r; if (d > DV - 1) d = DV - 1;   // row 2047 -> dup 2046 (unused)
        float4 v = __ldg((const float4*)(W + (size_t)d * DL + kbase) + c4);
        *((float4*)(ws + r * ZSTR) + c4) = v;
    }
    __syncthreads();

    float a0 = 0.f, a1 = 0.f, a2 = 0.f, a3 = 0.f;
    {
        const float4* zrow = (const float4*)(zs + lane * ZSTR);
        const float4* w0 = (const float4*)(ws + (w     ) * ZSTR);
        const float4* w1 = (const float4*)(ws + (w + 16) * ZSTR);
        const float4* w2 = (const float4*)(ws + (w + 32) * ZSTR);
        const float4* w3 = (const float4*)(ws + (w + 48) * ZSTR);
#pragma unroll 8
        for (int k = 0; k < KH / 4; k++) {
            float4 z = zrow[k];
            float4 p = w0[k];             // warp-uniform -> broadcast (1 cyc)
            a0 += z.x * p.x + z.y * p.y + z.z * p.z + z.w * p.w;
            float4 q = w1[k];
            a1 += z.x * q.x + z.y * q.y + z.z * q.z + z.w * q.w;
            float4 r = w2[k];
            a2 += z.x * r.x + z.y * r.y + z.z * r.z + z.w * r.w;
            float4 s = w3[k];
            a3 += z.x * s.x + z.y * s.y + z.z * s.z + z.w * s.w;
        }
    }
    __syncthreads();                      // zs free; reuse as transpose buffer

    // transpose partials [d_local][b] -> coalesced g_pre[kq][b][d] stores
    float* tr = zs;                       // [64][TSTR] = 8448B < zs area
    tr[(w     ) * TSTR + lane] = a0;
    tr[(w + 16) * TSTR + lane] = a1;
    tr[(w + 32) * TSTR + lane] = a2;
    tr[(w + 48) * TSTR + lane] = a3;
    __syncthreads();

#pragma unroll
    for (int idx = tid; idx < BATCH * DPC; idx += NT) {   // 4 iters
        int b = idx >> 6;                 // 0..31
        int c = idx & 63;                 // d_local
        g_pre[kq][b][dbase + c] = tr[c * TSTR + b];       // 128B-coalesced per warp
    }
}

// ---------------------------------------------------------------------------
// Solve: per-batch Cayley step, truncated Neumann series (error ~2e-8):
//   x = h + 2Nh + 2N^2h + 2N^3h,  (Nx)[i] = sv[i]*x[i+1] - sv[i-1]*x[i-1]
//   sv[i] = HALF_DT * tanh(sum_q g_pre[q][b][i] + bias[i]),  zero-padded edges.
// 32 CTAs x 512 threads, 3 stencil passes in smem.
// ---------------------------------------------------------------------------
#define EPT (DM / NT)   // 4

__global__ void __launch_bounds__(NT, 1)
solve_kernel(const float* __restrict__ h,
             const float* __restrict__ bias,
             float* __restrict__ out) {
    __shared__ float hs_s[DM + 2];
    __shared__ float sv_s[DM + 2];
    __shared__ float y1_s[DM + 2];
    __shared__ float y2_s[DM + 2];

    const int b   = blockIdx.x;
    const int tid = threadIdx.x;
    float* hp  = hs_s + 1;
    float* svp = sv_s + 1;
    float* y1  = y1_s + 1;
    float* y2  = y2_s + 1;

    if (tid == 0) {
        hp[-1] = 0.f;  hp[DM] = 0.f;
        svp[-1] = 0.f; svp[DV] = 0.f;
        y1[-1] = 0.f;  y1[DM] = 0.f;
        y2[-1] = 0.f;  y2[DM] = 0.f;
    }
    {
        const float4* hrow4 = (const float4*)(h + (size_t)b * DM);
        const float4* p04 = (const float4*)g_pre[0][b];
        const float4* p14 = (const float4*)g_pre[1][b];
        const float4* p24 = (const float4*)g_pre[2][b];
        const float4* p34 = (const float4*)g_pre[3][b];
        int i4 = tid;                       // 0..511, one float4 per thread
        int i  = i4 * 4;
        float4 hv = hrow4[i4];
        hp[i] = hv.x; hp[i+1] = hv.y; hp[i+2] = hv.z; hp[i+3] = hv.w;
        float4 q0 = p04[i4], q1 = p14[i4], q2 = p24[i4], q3 = p34[i4];
        float s0 = (q0.x + q1.x) + (q2.x + q3.x);
        float s1 = (q0.y + q1.y) + (q2.y + q3.y);
        float s2 = (q0.z + q1.z) + (q2.z + q3.z);
        float s3 = (q0.w + q1.w) + (q2.w + q3.w);
        svp[i]   = HALF_DT * tanhf(s0 + __ldg(&bias[i]));
        svp[i+1] = HALF_DT * tanhf(s1 + __ldg(&bias[i+1]));
        svp[i+2] = HALF_DT * tanhf(s2 + __ldg(&bias[i+2]));
        if (i + 3 < DV)                     // bias has 2047 elems; skip i=2047
            svp[i+3] = HALF_DT * tanhf(s3 + __ldg(&bias[i+3]));
    }
    __syncthreads();

    float acc[EPT];
#pragma unroll
    for (int j = 0; j < EPT; j++) {         // pass 1: y1 = N h
        int i = tid + j * NT;
        float t = svp[i] * hp[i + 1] - svp[i - 1] * hp[i - 1];
        y1[i] = t;
        acc[j] = hp[i] + 2.f * t;
    }
    __syncthreads();
#pragma unroll
    for (int j = 0; j < EPT; j++) {         // pass 2: y2 = N y1
        int i = tid + j * NT;
        float t = svp[i] * y1[i + 1] - svp[i - 1] * y1[i - 1];
        y2[i] = t;
        acc[j] += 2.f * t;
    }
    __syncthreads();
    float* orow = out + (size_t)b * DM;
#pragma unroll
    for (int j = 0; j < EPT; j++) {         // pass 3 + store
        int i = tid + j * NT;
        float t = svp[i] * y2[i + 1] - svp[i - 1] * y2[i - 1];
        orow[i] = acc[j] + 2.f * t;
    }
}

// ---------------------------------------------------------------------------
extern "C" void kernel_launch(void* const* d_in, const int* in_sizes, int n_in,
                              void* d_out, int out_size) {
    const float* z0   = (const float*)d_in[0];   // (32, 512)
    const float* h    = (const float*)d_in[1];   // (32, 2048)
    const float* W    = (const float*)d_in[2];   // (2047, 512)
    const float* bias = (const float*)d_in[3];   // (2047,)
    float* out = (float*)d_out;                  // (32, 2048)

    const int smemA = (BATCH + DPC) * ZSTR * (int)sizeof(float);   // 50688 B
    static bool attr_done = false;
    if (!attr_done) {
        cudaFuncSetAttribute(gemm_kernel,
                             cudaFuncAttributeMaxDynamicSharedMemorySize, smemA);
        attr_done = true;
    }
    gemm_kernel<<<GRID, NT, smemA>>>(z0, W);
    solve_kernel<<<BATCH, NT>>>(h, bias, out);
}